// round 9
// baseline (speedup 1.0000x reference)
#include <cuda_runtime.h>
#include <cuda_bf16.h>
#include <mma.h>
#include <stdint.h>

using namespace nvcuda;

#define NBATCH 4096
#define NN 64
#define NH 8
#define NL 3
#define TPB 512

// P: [160][72] bf16  (row r = b*5 + p; p: 0=x_hi,1=x_lo,2=x^2,3=x^3,4=x^4; col m)
// Mask: [64][64] bf16 row-major == (dag != 0)
// Sarr: [64 n][164] float  (col-major store of C[160,64]: Sarr[n*164 + r])
#define PLD   72
#define SLD   164
#define OFF_MASK 0
#define OFF_P    8192
#define OFF_XS   31232          // float[64][33]
#define OFF_SARR 39680          // float[64*164]
#define OFF_CNT  81664          // int[64]
#define OFF_CNTF 81920          // float[64]
#define OFF_CG   82176          // float2[24]
#define OFF_MLP  82368          // float[42]
#define OFF_LM   82544          // float[2]
#define SMEM_ALLOC 82688

__global__ void __launch_bounds__(TPB)
cat_wmma(const float* __restrict__ X, const int* __restrict__ dag,
         const float* __restrict__ Wk, const float* __restrict__ Wq,
         const float* __restrict__ Wv, const float* __restrict__ Wp,
         const float* __restrict__ bp, const float* __restrict__ W1,
         const float* __restrict__ b1, const float* __restrict__ W2,
         const float* __restrict__ b2, const float* __restrict__ Wlm,
         const float* __restrict__ blm, float* __restrict__ out)
{
    extern __shared__ char dsm[];
    __nv_bfloat16* Pm   = (__nv_bfloat16*)(dsm + OFF_P);
    __nv_bfloat16* Mk   = (__nv_bfloat16*)(dsm + OFF_MASK);
    float*  xs    = (float*)(dsm + OFF_XS);
    float*  Sarr  = (float*)(dsm + OFF_SARR);
    int*    scnt  = (int*)  (dsm + OFF_CNT);
    float*  scntf = (float*)(dsm + OFF_CNTF);
    float2* scg   = (float2*)(dsm + OFF_CG);
    float*  smlp  = (float*)(dsm + OFF_MLP);
    float*  slm   = (float*)(dsm + OFF_LM);

    const int tid  = threadIdx.x;
    const int w    = tid >> 5;
    const int lane = tid & 31;
    const size_t base = (size_t)blockIdx.x * 32 * 64;

    // ---- stage X: xs[m][b], stride 33 ----
    for (int i = tid; i < 32 * 64; i += TPB)
        xs[(i & 63) * 33 + (i >> 6)] = X[base + i];

    // ---- mask -> bf16 (B matrix: Mk[m][n] = dag[m][n] != 0) ----
    for (int i = tid; i < 64 * 64; i += TPB)
        Mk[i] = __float2bfloat16((dag[i] != 0) ? 1.f : 0.f);

    // ---- per-row counts via ballots ----
    #pragma unroll
    for (int r = 0; r < 4; r++) {
        const int n = w + r * 16;
        const int vlo = dag[lane * 64 + n];
        const int vhi = dag[(lane + 32) * 64 + n];
        const int cnt = __popc(__ballot_sync(0xffffffffu, vlo != 0)) +
                        __popc(__ballot_sync(0xffffffffu, vhi != 0));
        if (lane == 0) { scnt[n] = cnt; scntf[n] = (float)cnt; }
    }

    // ---- weight contractions ----
    if (tid < NL * NH) {
        const int l = tid >> 3, h = tid & 7;
        const float* q = Wq + tid * 16;
        const float* k = Wk + tid * 16;
        float s = 0.f;
        #pragma unroll
        for (int d = 0; d < 16; d++) s = fmaf(q[d], k[d], s);
        const float* v = Wv + tid * 16;
        const float* p = Wp + l * 128 + h * 16;
        float g = 0.f;
        #pragma unroll
        for (int d = 0; d < 16; d++) g = fmaf(v[d], p[d], g);
        scg[tid] = make_float2(s * 0.25f, g);        // scale = HS^-0.5
    } else if (tid >= 32 && tid < 32 + NL) {
        const int l = tid - 32;
        smlp[l * 14 + 0] = bp[l];
        #pragma unroll
        for (int j = 0; j < 4; j++) {
            smlp[l * 14 + 1 + j] = W1[l * 4 + j];
            smlp[l * 14 + 5 + j] = b1[l * 4 + j];
            smlp[l * 14 + 9 + j] = W2[l * 4 + j];
        }
        smlp[l * 14 + 13] = b2[l];
    } else if (tid == 40) {
        slm[0] = Wlm[0]; slm[1] = blm[0];
    }
    __syncthreads();

    #pragma unroll 1
    for (int l = 0; l < NL; l++) {
        // ---- build P (warp-uniform r per iteration; lanes span m) ----
        for (int i = tid; i < 160 * 64; i += TPB) {
            const int r = i >> 6;            // uniform within warp
            const int m = i & 63;
            const int b = r / 5;
            const int p = r - b * 5;
            const float x = xs[m * 33 + b];
            __nv_bfloat16 hv;
            if (p == 0) {
                hv = __float2bfloat16(x);
            } else if (p == 1) {
                hv = __float2bfloat16(x - __bfloat162float(__float2bfloat16(x)));
            } else {
                const float x2 = x * x;
                hv = __float2bfloat16(p == 2 ? x2 : (p == 3 ? x2 * x : x2 * x2));
            }
            Pm[r * PLD + m] = hv;
        }
        __syncthreads();

        // ---- moments GEMM: C[160,64] = P @ Mask (K=64), 40 tiles over 16 warps ----
        for (int id = w; id < 40; id += 16) {
            const int rt = id >> 2, nt = id & 3;
            wmma::fragment<wmma::accumulator, 16, 16, 16, float> fc;
            wmma::fill_fragment(fc, 0.f);
            #pragma unroll
            for (int kt = 0; kt < 4; kt++) {
                wmma::fragment<wmma::matrix_a, 16, 16, 16, __nv_bfloat16, wmma::row_major> fa;
                wmma::fragment<wmma::matrix_b, 16, 16, 16, __nv_bfloat16, wmma::row_major> fb;
                wmma::load_matrix_sync(fa, Pm + rt * 16 * PLD + kt * 16, PLD);
                wmma::load_matrix_sync(fb, Mk + kt * 16 * 64 + nt * 16, 64);
                wmma::mma_sync(fc, fa, fb, fc);
            }
            wmma::store_matrix_sync(Sarr + nt * 16 * SLD + rt * 16, fc, SLD,
                                    wmma::mem_col_major);
        }
        __syncthreads();

        // ---- epilogue: lane = batch, rows n = w + r*16 ----
        const float2* cgl = &scg[l * NH];
        const float*  ml  = &smlp[l * 14];
        #pragma unroll 1
        for (int r = 0; r < 4; r++) {
            const int n = w + r * 16;
            const float* sp = &Sarr[n * SLD + lane * 5];   // stride-5: conflict-free
            const float S1 = sp[0] + sp[1];                // hi + lo
            const float S2 = sp[2];
            const float S3 = sp[3];
            const float S4 = sp[4];
            const float xn = xs[n * 33 + lane];
            // deg-3 Taylor (matches R6, rel_err 9e-8 with exact moments):
            // se = S0 + t S1 + t^2/2 S2 + t^3/6 S3 ; sx = S1 + t S2 + t^2/2 S3 + t^3/6 S4
            const float a0 = scntf[n];
            const float a2 = S2 * 0.5f, a3 = S3 * (1.f / 6.f);
            const float b2c = S3 * 0.5f, b3 = S4 * (1.f / 6.f);
            float delta = 0.f;
            #pragma unroll
            for (int h = 0; h < NH; h++) {
                const float2 cg = cgl[h];
                const float t = cg.x * xn;
                const float se = fmaf(fmaf(fmaf(a3, t, a2), t, S1), t, a0);
                const float sx = fmaf(fmaf(fmaf(b3, t, b2c), t, S2), t, S1);
                delta = fmaf(cg.y, __fdividef(sx, se), delta);
            }
            if (scnt[n] == 0) delta = 0.f;                 // kill 0/0

            const float xv = xn + delta + ml[0];
            float acc = xv + ml[13];
            #pragma unroll
            for (int j = 0; j < 4; j++)
                acc = fmaf(fmaxf(fmaf(xv, ml[1 + j], ml[5 + j]), 0.f), ml[9 + j], acc);
            xs[n * 33 + lane] = acc;                       // own cell only
        }
        __syncthreads();
    }

    // ---- output ----
    const float wlmv = slm[0], blmv = slm[1];
    for (int i = tid; i < 32 * 64; i += TPB)
        out[base + i] = fmaf(xs[(i & 63) * 33 + (i >> 6)], wlmv, blmv);
}

// ---------------- launch ----------------
extern "C" void kernel_launch(void* const* d_in, const int* in_sizes, int n_in,
                              void* d_out, int out_size)
{
    const float* X   = (const float*)d_in[0];
    const int*   dag = (const int*)  d_in[1];
    const float* Wk  = (const float*)d_in[2];
    const float* Wq  = (const float*)d_in[3];
    const float* Wv  = (const float*)d_in[4];
    const float* Wp  = (const float*)d_in[5];
    const float* bp  = (const float*)d_in[6];
    const float* W1  = (const float*)d_in[7];
    const float* b1  = (const float*)d_in[8];
    const float* W2  = (const float*)d_in[9];
    const float* b2  = (const float*)d_in[10];
    const float* Wlm = (const float*)d_in[11];
    const float* blm = (const float*)d_in[12];
    float* out = (float*)d_out;

    cudaFuncSetAttribute(cat_wmma, cudaFuncAttributeMaxDynamicSharedMemorySize, SMEM_ALLOC);
    cat_wmma<<<NBATCH / 32, TPB, SMEM_ALLOC>>>(X, dag, Wk, Wq, Wv, Wp, bp, W1, b1, W2, b2,
                                               Wlm, blm, out);
}

// round 11
// speedup vs baseline: 1.1488x; 1.1488x over previous
#include <cuda_runtime.h>
#include <cuda_bf16.h>
#include <mma.h>
#include <stdint.h>

using namespace nvcuda;

#define NBATCH 4096
#define NN 64
#define NH 8
#define NL 3
#define TPB 128
#define BPC 8            // batches per CTA
#define PLD 72           // P row stride (bf16)
#define SLD 52           // Sarr column stride (float)

// P rows: r = b*6 + p, p: 0=x_hi, 1=x_lo, 2=x^2, 3=x^3, 4=x^4, 5=ones (-> S0)
// C[48,64] = P @ Mask;  Sarr[n*SLD + r] = C[r][n]  (col-major store)

__global__ void __launch_bounds__(TPB)
cat_wmma(const float* __restrict__ X, const int* __restrict__ dag,
         const float* __restrict__ Wk, const float* __restrict__ Wq,
         const float* __restrict__ Wv, const float* __restrict__ Wp,
         const float* __restrict__ bp, const float* __restrict__ W1,
         const float* __restrict__ b1, const float* __restrict__ W2,
         const float* __restrict__ b2, const float* __restrict__ Wlm,
         const float* __restrict__ blm, float* __restrict__ out)
{
    __shared__ __align__(32) __nv_bfloat16 Mk[64 * 64];   // Mk[m*64+n] = dag[m][n] != 0
    __shared__ __align__(32) __nv_bfloat16 Pm[48 * PLD];
    __shared__ __align__(32) float         Sarr[64 * SLD];
    __shared__ float  xs[64 * 9];                          // xs[m*9 + b]
    __shared__ float2 scg[NL * NH];                        // (ch, gh)
    __shared__ float  smlp[NL * 14];
    __shared__ float  slm[2];

    const int tid = threadIdx.x;
    const int w   = tid >> 5;
    const size_t base = (size_t)blockIdx.x * BPC * 64;

    // ---- stage X (coalesced) ----
    #pragma unroll
    for (int i = tid; i < BPC * 64; i += TPB)
        xs[(i & 63) * 9 + (i >> 6)] = X[base + i];

    // ---- mask -> bf16 ----
    #pragma unroll 4
    for (int i = tid; i < 64 * 64; i += TPB)
        Mk[i] = __float2bfloat16((dag[i] != 0) ? 1.f : 0.f);

    // ---- weight contractions ----
    if (tid < NL * NH) {
        const int l = tid >> 3, h = tid & 7;
        const float* q = Wq + tid * 16;
        const float* k = Wk + tid * 16;
        float s = 0.f;
        #pragma unroll
        for (int d = 0; d < 16; d++) s = fmaf(q[d], k[d], s);
        const float* v = Wv + tid * 16;
        const float* p = Wp + l * 128 + h * 16;
        float g = 0.f;
        #pragma unroll
        for (int d = 0; d < 16; d++) g = fmaf(v[d], p[d], g);
        scg[tid] = make_float2(s * 0.25f, g);              // scale = HS^-0.5
    } else if (tid >= 32 && tid < 32 + NL) {
        const int l = tid - 32;
        smlp[l * 14 + 0] = bp[l];
        #pragma unroll
        for (int j = 0; j < 4; j++) {
            smlp[l * 14 + 1 + j] = W1[l * 4 + j];
            smlp[l * 14 + 5 + j] = b1[l * 4 + j];
            smlp[l * 14 + 9 + j] = W2[l * 4 + j];
        }
        smlp[l * 14 + 13] = b2[l];
    } else if (tid == 40) {
        slm[0] = Wlm[0]; slm[1] = blm[0];
    }
    __syncthreads();

    const __nv_bfloat16 ONE = __float2bfloat16(1.f);

    #pragma unroll 1
    for (int l = 0; l < NL; l++) {
        // ---- build P pair-wise: thread -> (m, b), writes 6 power rows ----
        #pragma unroll
        for (int i = tid; i < 64 * BPC; i += TPB) {
            const int m = i >> 3, b = i & 7;
            const float x = xs[m * 9 + b];
            const __nv_bfloat16 hx = __float2bfloat16(x);
            const float x2 = x * x;
            __nv_bfloat16* pr = &Pm[b * 6 * PLD + m];
            pr[0 * PLD] = hx;
            pr[1 * PLD] = __float2bfloat16(x - __bfloat162float(hx));
            pr[2 * PLD] = __float2bfloat16(x2);
            pr[3 * PLD] = __float2bfloat16(x2 * x);
            pr[4 * PLD] = __float2bfloat16(x2 * x2);
            pr[5 * PLD] = ONE;
        }
        __syncthreads();

        // ---- moments GEMM: C[48,64] = P @ Mask; 12 tiles over 4 warps ----
        for (int id = w; id < 12; id += 4) {
            const int rt = id >> 2, nt = id & 3;
            wmma::fragment<wmma::accumulator, 16, 16, 16, float> fc;
            wmma::fill_fragment(fc, 0.f);
            #pragma unroll
            for (int kt = 0; kt < 4; kt++) {
                wmma::fragment<wmma::matrix_a, 16, 16, 16, __nv_bfloat16, wmma::row_major> fa;
                wmma::fragment<wmma::matrix_b, 16, 16, 16, __nv_bfloat16, wmma::row_major> fb;
                wmma::load_matrix_sync(fa, Pm + rt * 16 * PLD + kt * 16, PLD);
                wmma::load_matrix_sync(fb, Mk + kt * 16 * 64 + nt * 16, 64);
                wmma::mma_sync(fc, fa, fb, fc);
            }
            wmma::store_matrix_sync(Sarr + nt * 16 * SLD + rt * 16, fc, SLD,
                                    wmma::mem_col_major);
        }
        __syncthreads();

        // ---- epilogue: thread -> (b = tid&7, ngrp = tid>>3); 4 rows each ----
        const float2* cgl = &scg[l * NH];
        const float*  ml  = &smlp[l * 14];
        const int b    = tid & 7;
        const int ngrp = tid >> 3;
        #pragma unroll 1
        for (int r = 0; r < 4; r++) {
            const int n = ngrp + r * 16;
            const float* sp = &Sarr[n * SLD + b * 6];
            const float S1 = sp[0] + sp[1];                // hi + lo
            const float S2 = sp[2];
            const float S3 = sp[3];
            const float S4 = sp[4];
            const float S0 = sp[5];                        // exact count from ones-row
            const float xn = xs[n * 9 + b];
            // deg-3 Taylor: se = S0 + t S1 + t^2/2 S2 + t^3/6 S3
            //               sx = S1 + t S2 + t^2/2 S3 + t^3/6 S4
            const float a2 = S2 * 0.5f, a3 = S3 * (1.f / 6.f);
            const float b2c = S3 * 0.5f, b3 = S4 * (1.f / 6.f);
            float delta = 0.f;
            #pragma unroll
            for (int h = 0; h < NH; h++) {
                const float2 cg = cgl[h];
                const float t = cg.x * xn;
                const float se = fmaf(fmaf(fmaf(a3, t, a2), t, S1), t, S0);
                const float sx = fmaf(fmaf(fmaf(b3, t, b2c), t, S2), t, S1);
                delta = fmaf(cg.y, __fdividef(sx, se), delta);
            }
            if (S0 == 0.f) delta = 0.f;                    // kill 0/0 (empty row)

            const float xv = xn + delta + ml[0];
            float acc = xv + ml[13];
            #pragma unroll
            for (int j = 0; j < 4; j++)
                acc = fmaf(fmaxf(fmaf(xv, ml[1 + j], ml[5 + j]), 0.f), ml[9 + j], acc);
            xs[n * 9 + b] = acc;                           // own cell only
        }
        __syncthreads();
    }

    // ---- output ----
    const float wlmv = slm[0], blmv = slm[1];
    #pragma unroll
    for (int i = tid; i < BPC * 64; i += TPB)
        out[base + i] = fmaf(xs[(i & 63) * 9 + (i >> 6)], wlmv, blmv);
}

// ---------------- launch: single kernel ----------------
extern "C" void kernel_launch(void* const* d_in, const int* in_sizes, int n_in,
                              void* d_out, int out_size)
{
    const float* X   = (const float*)d_in[0];
    const int*   dag = (const int*)  d_in[1];
    const float* Wk  = (const float*)d_in[2];
    const float* Wq  = (const float*)d_in[3];
    const float* Wv  = (const float*)d_in[4];
    const float* Wp  = (const float*)d_in[5];
    const float* bp  = (const float*)d_in[6];
    const float* W1  = (const float*)d_in[7];
    const float* b1  = (const float*)d_in[8];
    const float* W2  = (const float*)d_in[9];
    const float* b2  = (const float*)d_in[10];
    const float* Wlm = (const float*)d_in[11];
    const float* blm = (const float*)d_in[12];
    float* out = (float*)d_out;

    cat_wmma<<<NBATCH / BPC, TPB>>>(X, dag, Wk, Wq, Wv, Wp, bp, W1, b1, W2, b2,
                                    Wlm, blm, out);
}